// round 10
// baseline (speedup 1.0000x reference)
#include <cuda_runtime.h>
#include <cstdint>
#include <float.h>

// Problem shape (fixed by the reference)
#define NS   16384   // samples
#define DIN  512     // input dim
#define NF   256     // feature dim
#define NC   1000    // classes
#define NCP  1024    // padded classes
#define NTHR 1024

// meansT [k][class] fp32, zero-padded to 1024 classes (one-time transpose)
__device__ __align__(16) float g_mT[NF * NCP];

// ---------------- smem layout (floats), phases overlap ----------------
#define AS1_STRIDE 132
#define AS1_ELEMS  (32 * AS1_STRIDE)        // x chunk, k-major, x2 buffers
#define WS_ELEMS   (32 * 256)               // W chunk [k][n], x2 buffers
#define AS2_STRIDE 132
#define AS2_ELEMS  (256 * AS2_STRIDE)       // F block, k-major (33792)
#define BS_STRIDE  260
#define BS_ELEMS   (32 * BS_STRIDE)         // meansT chunk [k][c], x2 (8320)
#define SMEM_FLOATS (AS2_ELEMS + 2 * BS_ELEMS)   // 50432
#define SMEM_BYTES  (SMEM_FLOATS * 4)            // 201728
static_assert(2 * AS1_ELEMS + 2 * WS_ELEMS <= SMEM_FLOATS, "phase1 fits");

// ---------------- f32x2 packed-FMA helpers (Blackwell) ----------------
__device__ __forceinline__ void ffma2(unsigned long long& acc,
                                      unsigned long long a,
                                      unsigned long long b) {
    asm("fma.rn.f32x2 %0, %1, %2, %0;" : "+l"(acc) : "l"(a), "l"(b));
}
__device__ __forceinline__ unsigned long long pack2(float x) {
    unsigned long long r;
    asm("mov.b64 %0, {%1, %1};" : "=l"(r) : "f"(x));
    return r;
}
__device__ __forceinline__ float2 unpack2(unsigned long long v) {
    float2 f;
    asm("mov.b64 {%0, %1}, %2;" : "=f"(f.x), "=f"(f.y) : "l"(v));
    return f;
}
__device__ __forceinline__ unsigned smem_u32(const void* p) {
    return (unsigned)__cvta_generic_to_shared(p);
}
__device__ __forceinline__ void cp16(unsigned dst, const float* src) {
    asm volatile("cp.async.ca.shared.global [%0], [%1], 16;" :: "r"(dst), "l"(src));
}
#define CP_COMMIT() asm volatile("cp.async.commit_group;")
#define CP_WAIT0()  asm volatile("cp.async.wait_group 0;")

// =====================================================================
// One-time: meansT[k][c] = means[c][k], zero-pad c >= NC. Tiled transpose.
// =====================================================================
__global__ void k_prep(const float* __restrict__ means) {
    __shared__ float tile[32][33];
    const int c0 = blockIdx.x * 32, k0 = blockIdx.y * 32;
    const int tx = threadIdx.x, ty = threadIdx.y;   // 32 x 8
#pragma unroll
    for (int i = 0; i < 32; i += 8) {
        int c = c0 + ty + i;
        tile[ty + i][tx] = (c < NC) ? means[(size_t)c * NF + k0 + tx] : 0.f;
    }
    __syncthreads();
#pragma unroll
    for (int i = 0; i < 32; i += 8)
        g_mT[(size_t)(k0 + ty + i) * NCP + c0 + tx] = tile[tx][ty + i];
}

// =====================================================================
// Fused kernel: 1024 threads per CTA over 128 sample rows.
// Layout: lane tx -> 4 rows (distinct LDS, f32x2 row pairs),
//         warp w  -> 8-wide column group (warp-UNIFORM b loads).
//   Phase 1: F = x_blk[128,512] @ W[512,256]   (4x8 reg tile)
//   Phase 2: S = F @ meansT[256,1024], running argmax, one-hot write
// =====================================================================
__global__ __launch_bounds__(NTHR, 1) void k_fused(const float* __restrict__ x,
                                                   const float* __restrict__ W,
                                                   float* __restrict__ out) {
    extern __shared__ float sm[];
    __shared__ unsigned long long best[128];

    const int t     = threadIdx.x;
    const int tx    = t & 31;
    const int w     = t >> 5;         // 0..31
    const int rbase = tx * 4;         // 4 rows per lane (2 f32x2 pairs)
    const int nbase = w * 8;          // 8 cols per warp (uniform)
    const int m0    = blockIdx.x * 128;

    if (t < 128) best[t] = 0ull;

    // ================= Phase 1: F = x_blk @ W =================
    float* As1 = sm;                    // [2][32][132] k-major x chunk
    float* Ws  = sm + 2 * AS1_ELEMS;    // [2][32][256] W chunk

    const int xrow = t >> 3;            // 0..127
    const int xkq  = (t & 7) * 4;       // k offset within 32-chunk
    float4 xr;

    // ---- prologue: chunk 0 ----
    {
        const float* src = W;
#pragma unroll
        for (int i = 0; i < 2; i++) {
            int q = t + i * NTHR;
            int kk = q >> 6, nq = q & 63;
            cp16(smem_u32(Ws + kk * 256 + nq * 4), src + (size_t)kk * NF + nq * 4);
        }
        CP_COMMIT();
        xr = *reinterpret_cast<const float4*>(&x[(size_t)(m0 + xrow) * DIN + xkq]);
        As1[(xkq + 0) * AS1_STRIDE + xrow] = xr.x;
        As1[(xkq + 1) * AS1_STRIDE + xrow] = xr.y;
        As1[(xkq + 2) * AS1_STRIDE + xrow] = xr.z;
        As1[(xkq + 3) * AS1_STRIDE + xrow] = xr.w;
        CP_WAIT0();
        __syncthreads();
    }

    unsigned long long acc1[2][8];
#pragma unroll
    for (int p = 0; p < 2; p++)
#pragma unroll
        for (int c = 0; c < 8; c++) acc1[p][c] = 0ull;

#pragma unroll 1
    for (int ch = 0; ch < 16; ch++) {
        if (ch + 1 < 16) {
            float* dst = Ws + ((ch + 1) & 1) * WS_ELEMS;
            const float* src = W + (size_t)(ch + 1) * 32 * NF;
#pragma unroll
            for (int i = 0; i < 2; i++) {
                int q = t + i * NTHR;
                int kk = q >> 6, nq = q & 63;
                cp16(smem_u32(dst + kk * 256 + nq * 4), src + (size_t)kk * NF + nq * 4);
            }
            CP_COMMIT();
            xr = *reinterpret_cast<const float4*>(
                &x[(size_t)(m0 + xrow) * DIN + (ch + 1) * 32 + xkq]);
        }
        const float* Ac = As1 + (ch & 1) * AS1_ELEMS;
        const float* Wc = Ws + (ch & 1) * WS_ELEMS;
#pragma unroll 4
        for (int k = 0; k < 32; k++) {
            ulonglong2 a = *reinterpret_cast<const ulonglong2*>(&Ac[k * AS1_STRIDE + rbase]);
            float4 b0 = *reinterpret_cast<const float4*>(&Wc[k * 256 + nbase]);      // uniform
            float4 b1 = *reinterpret_cast<const float4*>(&Wc[k * 256 + nbase + 4]);  // uniform
            unsigned long long bb[8] = {pack2(b0.x), pack2(b0.y), pack2(b0.z), pack2(b0.w),
                                        pack2(b1.x), pack2(b1.y), pack2(b1.z), pack2(b1.w)};
#pragma unroll
            for (int c = 0; c < 8; c++) {
                ffma2(acc1[0][c], a.x, bb[c]);
                ffma2(acc1[1][c], a.y, bb[c]);
            }
        }
        if (ch + 1 < 16) {
            float* An = As1 + ((ch + 1) & 1) * AS1_ELEMS;
            An[(xkq + 0) * AS1_STRIDE + xrow] = xr.x;
            An[(xkq + 1) * AS1_STRIDE + xrow] = xr.y;
            An[(xkq + 2) * AS1_STRIDE + xrow] = xr.z;
            An[(xkq + 3) * AS1_STRIDE + xrow] = xr.w;
            CP_WAIT0();
            __syncthreads();
        }
    }
    __syncthreads();   // all phase-1 smem reads done before As2 overwrite

    // ======= Transition: F (regs) -> As2 (k-major smem) =======
    float* As2 = sm;                 // [256][132]
    float* Bs  = sm + AS2_ELEMS;     // [2][32][260]
#pragma unroll
    for (int c = 0; c < 8; c++) {
#pragma unroll
        for (int p = 0; p < 2; p++) {
            float2 u = unpack2(acc1[p][c]);
            *reinterpret_cast<float2*>(&As2[(nbase + c) * AS2_STRIDE + rbase + 2 * p]) = u;
        }
    }

    // ---- B(0) prologue ----
    {
#pragma unroll
        for (int i = 0; i < 2; i++) {
            int q = t + i * NTHR;
            int kk = q >> 6, cq = q & 63;
            cp16(smem_u32(Bs + kk * BS_STRIDE + cq * 4), g_mT + (size_t)kk * NCP + cq * 4);
        }
        CP_COMMIT();
        CP_WAIT0();
        __syncthreads();   // As2 visible + B(0) landed
    }

    // ================= Phase 2: scores + argmax =================
    float bv[4];
    int   bi[4];
#pragma unroll
    for (int r = 0; r < 4; r++) { bv[r] = -FLT_MAX; bi[r] = 0x7FFFFFFF; }

    unsigned long long acc2[2][8];

#pragma unroll 1
    for (int ch = 0; ch < 32; ch++) {          // ch = ct*8 + kq (ct: 256-cls tile)
        const int ct = ch >> 3, kq = ch & 7;
        if (ch + 1 < 32) {
            int ct2 = (ch + 1) >> 3, kq2 = (ch + 1) & 7;
            float* dst = Bs + ((ch + 1) & 1) * BS_ELEMS;
            const float* src = g_mT + (size_t)(kq2 * 32) * NCP + ct2 * 256;
#pragma unroll
            for (int i = 0; i < 2; i++) {
                int q = t + i * NTHR;
                int kk = q >> 6, cq = q & 63;
                cp16(smem_u32(dst + kk * BS_STRIDE + cq * 4), src + (size_t)kk * NCP + cq * 4);
            }
            CP_COMMIT();
        }

        if (kq == 0) {
#pragma unroll
            for (int p = 0; p < 2; p++)
#pragma unroll
                for (int c = 0; c < 8; c++) acc2[p][c] = 0ull;
        }

        const float* Ab = As2 + kq * 32 * AS2_STRIDE;
        const float* Bc = Bs + (ch & 1) * BS_ELEMS;
#pragma unroll 4
        for (int kk = 0; kk < 32; kk++) {
            ulonglong2 a = *reinterpret_cast<const ulonglong2*>(&Ab[kk * AS2_STRIDE + rbase]);
            float4 b0 = *reinterpret_cast<const float4*>(&Bc[kk * BS_STRIDE + nbase]);      // uniform
            float4 b1 = *reinterpret_cast<const float4*>(&Bc[kk * BS_STRIDE + nbase + 4]);  // uniform
            unsigned long long bb[8] = {pack2(b0.x), pack2(b0.y), pack2(b0.z), pack2(b0.w),
                                        pack2(b1.x), pack2(b1.y), pack2(b1.z), pack2(b1.w)};
#pragma unroll
            for (int c = 0; c < 8; c++) {
                ffma2(acc2[0][c], a.x, bb[c]);
                ffma2(acc2[1][c], a.y, bb[c]);
            }
        }

        if (kq == 7) {
            const int cb = ct * 256 + nbase;
#pragma unroll
            for (int c = 0; c < 8; c++) {       // ascending class order
                int cls = cb + c;
                if (cls < NC) {
#pragma unroll
                    for (int p = 0; p < 2; p++) {
                        float2 u = unpack2(acc2[p][c]);
                        // strict > keeps lowest class on ties (torch argmin)
                        if (u.x > bv[2 * p])     { bv[2 * p]     = u.x; bi[2 * p]     = cls; }
                        if (u.y > bv[2 * p + 1]) { bv[2 * p + 1] = u.y; bi[2 * p + 1] = cls; }
                    }
                }
            }
        }
        if (ch + 1 < 32) {
            CP_WAIT0();
            __syncthreads();
        }
    }

    // Cross-warp argmax: packed (monotonic-float | ~idx) 64-bit atomicMax.
#pragma unroll
    for (int lr = 0; lr < 4; lr++) {
        unsigned u = __float_as_uint(bv[lr]);
        u ^= ((unsigned)((int)u >> 31)) | 0x80000000u;   // order-preserving map
        unsigned long long key = ((unsigned long long)u << 32) |
                                 (unsigned long long)(0xFFFFFFFFu - (unsigned)bi[lr]);
        atomicMax(&best[rbase + lr], key);
    }
    __syncthreads();

    // One-hot: coalesced float4 zero-fill, then scatter 1.0f.
    const float4 z4 = make_float4(0.f, 0.f, 0.f, 0.f);
#pragma unroll 1
    for (int i = t; i < 128 * 256; i += NTHR) {
        int row = i >> 8, c = i & 255;
        if (c < 250)
            *reinterpret_cast<float4*>(&out[(size_t)(m0 + row) * NC + c * 4]) = z4;
    }
    __syncthreads();
    if (t < 128) {
        unsigned idx = 0xFFFFFFFFu - (unsigned)(best[t] & 0xFFFFFFFFull);
        out[(size_t)(m0 + t) * NC + idx] = 1.0f;
    }
}

// =====================================================================
extern "C" void kernel_launch(void* const* d_in, const int* in_sizes, int n_in,
                              void* d_out, int out_size) {
    const float* x     = (const float*)d_in[0];  // [16384, 512]
    const float* W     = (const float*)d_in[1];  // [512, 256]
    const float* means = (const float*)d_in[2];  // [1000, 256]
    float* out = (float*)d_out;                  // [16384, 1000]
    (void)in_sizes; (void)n_in; (void)out_size;

    cudaFuncSetAttribute(k_fused, cudaFuncAttributeMaxDynamicSharedMemorySize,
                         SMEM_BYTES);
    k_prep<<<dim3(NCP / 32, NF / 32), dim3(32, 8)>>>(means);
    k_fused<<<NS / 128, NTHR, SMEM_BYTES>>>(x, W, out);
}